// round 5
// baseline (speedup 1.0000x reference)
#include <cuda_runtime.h>
#include <cuda_fp16.h>

#define NT      512     // threads per CTA
#define NCTA    128     // CTAs (2 samples each)
#define TS      512     // time steps
#define HDIM    128
#define DIN     64
#define G3      384
#define WPITCH  132     // padded W_hh row pitch (floats)

// shared memory layout (float offsets)
#define OFF_WHH   0
#define OFF_H     50688
#define OFF_HA    50944
#define OFF_HB    51200
#define OFF_HODE  51456
#define OFF_GGH   51712
#define OFF_GGI   52480
#define OFF_INP   53248
#define OFF_OUT   53376
#define OFF_DT    53504
#define OFF_BN    54016
#define OFF_BIH   54144
#define OFF_BHH   54528
#define OFF_BOUT  54912
#define OFF_MASK  54976
#define SMEM_FLOATS 55104
#define SMEM_BYTES  (SMEM_FLOATS * 4)

__device__ __forceinline__ float tanh_fast(float v) {
    float y;
    asm("tanh.approx.f32 %0, %1;" : "=f"(y) : "f"(v));
    return y;
}
__device__ __forceinline__ float sigm(float v) {
    return 1.0f / (1.0f + __expf(-v));
}
__device__ __forceinline__ float tanh_acc(float v) {
    // accurate to ~1e-7 abs via __expf; saturates correctly at +/-1
    return 1.0f - 2.0f / (__expf(2.0f * v) + 1.0f);
}

__global__ void __launch_bounds__(NT, 1)
gruode_persist(const float* __restrict__ x,
               const float* __restrict__ tp,
               const unsigned int* __restrict__ maskw,
               const float* __restrict__ Wih,
               const float* __restrict__ Whh,
               const float* __restrict__ bih,
               const float* __restrict__ bhh,
               const float* __restrict__ Wnode,
               const float* __restrict__ bnode,
               const float* __restrict__ Wout,
               const float* __restrict__ bout,
               float* __restrict__ out)
{
    extern __shared__ float sm[];
    const int tid = threadIdx.x;
    const int cta = blockIdx.x;
    const int sg0 = cta * 2;           // first global sample of this CTA

    // ---------------- init: W_hh -> smem (padded pitch) ----------------
    for (int idx = tid; idx < G3 * HDIM; idx += NT) {
        int r = idx >> 7, k = idx & 127;
        sm[OFF_WHH + r * WPITCH + k] = Whh[idx];
    }
    for (int i = tid; i < HDIM; i += NT) sm[OFF_BN + i] = bnode[i];
    for (int i = tid; i < G3;   i += NT) { sm[OFF_BIH + i] = bih[i]; sm[OFF_BHH + i] = bhh[i]; }
    for (int i = tid; i < DIN;  i += NT) sm[OFF_BOUT + i] = bout[i];
    if (tid < TS) sm[OFF_DT + tid] = (tid == 0) ? 0.01f : (tp[tid] - tp[tid - 1]);

    // samp_mask layout detection: 0=int32, 1=byte, 2=float32
    __shared__ int layoutFlag;
    if (tid == 0) {
        int fl = 0;
        for (int i = 0; i < 128; i++) {      // first 512 bytes: safe in all layouts
            unsigned w = maskw[i];
            if (w == 0x3F800000u) { fl = 2; break; }
            if (w > 1u) fl = 1;
        }
        layoutFlag = fl;
    }
    __syncthreads();
    {
        int fl = layoutFlag;
        char* mk = (char*)&sm[OFF_MASK];
        if (tid < TS) {
            bool m;
            if (fl == 1)      m = ((const unsigned char*)maskw)[tid] != 0;
            else if (fl == 2) m = ((const float*)maskw)[tid] != 0.0f;
            else              m = maskw[tid] != 0u;
            mk[tid] = m ? 1 : 0;
        }
    }

    // ---------------- register-resident weights ----------------
    // W_node: thread (jn = tid>>2, ksn = tid&3) owns W_node[jn][ksn*32 .. +32),
    // stored in the k-rotated read order (rotation kills h-read bank conflicts).
    const int jn = tid >> 2, ksn = tid & 3;
    float wn[32];
    #pragma unroll
    for (int kk = 0; kk < 8; kk++) {
        int rot = (kk + 2 * ksn) & 7;
        #pragma unroll
        for (int c = 0; c < 4; c++)
            wn[kk * 4 + c] = Wnode[jn * HDIM + ksn * 32 + rot * 4 + c];
    }
    // W_ih fp16: row-thread tid<384 owns full row (64 halfs = 32 half2)
    __half2 wih[32];
    if (tid < G3) {
        #pragma unroll
        for (int i = 0; i < 32; i++)
            wih[i] = __floats2half2_rn(Wih[tid * DIN + 2 * i], Wih[tid * DIN + 2 * i + 1]);
    }
    // W_out: thread (jo = tid>>3, kso = tid&7) owns W_out[jo][kso*16 .. +16), rotated
    const int jo = tid >> 3, kso = tid & 7;
    float wo[16];
    #pragma unroll
    for (int kk = 0; kk < 4; kk++) {
        int rot = (kk + (kso >> 1)) & 3;
        #pragma unroll
        for (int c = 0; c < 4; c++)
            wo[kk * 4 + c] = Wout[jo * HDIM + kso * 16 + rot * 4 + c];
    }

    // ---------------- state init ----------------
    if (tid < 256) sm[OFF_H + tid] = 0.0f;                      // h0 = 0
    if (tid < 128) sm[OFF_OUT + tid] = sm[OFF_BOUT + (tid & 63)]; // prev_out(0) = b_out

    // prefetch x for t=0 (threads 0..127: s = tid>>6, c = tid&63)
    const int sL = tid >> 6, cL = tid & 63;
    float xv = 0.0f;
    if (tid < 128) xv = x[(long)(sg0 + sL) * TS * DIN + cL];
    __syncthreads();

    const char* mk = (const char*)&sm[OFF_MASK];

    // ============================ time loop ============================
    for (int t = 0; t < TS; t++) {
        const float dt = sm[OFF_DT + t];

        // inp = use_x ? x[t] : prev_out   (prev_out = out row of t-1, in OFF_OUT)
        if (tid < 128) {
            float pv = sm[OFF_OUT + tid];
            sm[OFF_INP + tid] = mk[t] ? xv : pv;
        }

        // -------- RK4: dh/dt = tanh(h @ Wn^T + bn), 4 sub-steps --------
        float ks0 = 0.0f, ks1 = 0.0f;
        int srcOff = OFF_H;
        #pragma unroll
        for (int sub = 0; sub < 4; sub++) {
            float a00 = 0, a01 = 0, a02 = 0, a03 = 0;
            float a10 = 0, a11 = 0, a12 = 0, a13 = 0;
            #pragma unroll
            for (int kk = 0; kk < 8; kk++) {
                int rot = (kk + 2 * ksn) & 7;
                const float4 h0 = *(const float4*)&sm[srcOff + ksn * 32 + rot * 4];
                const float4 h1 = *(const float4*)&sm[srcOff + HDIM + ksn * 32 + rot * 4];
                float w0 = wn[kk * 4 + 0], w1 = wn[kk * 4 + 1];
                float w2 = wn[kk * 4 + 2], w3 = wn[kk * 4 + 3];
                a00 += w0 * h0.x; a01 += w1 * h0.y; a02 += w2 * h0.z; a03 += w3 * h0.w;
                a10 += w0 * h1.x; a11 += w1 * h1.y; a12 += w2 * h1.z; a13 += w3 * h1.w;
            }
            float y0 = (a00 + a01) + (a02 + a03);
            float y1 = (a10 + a11) + (a12 + a13);
            // reduce 4 ksegs (lanes differing in low 2 bits)
            y0 += __shfl_xor_sync(0xffffffffu, y0, 1);
            y0 += __shfl_xor_sync(0xffffffffu, y0, 2);
            y1 += __shfl_xor_sync(0xffffffffu, y1, 1);
            y1 += __shfl_xor_sync(0xffffffffu, y1, 2);
            float bn = sm[OFF_BN + jn];
            float k0 = tanh_fast(y0 + bn);
            float k1 = tanh_fast(y1 + bn);
            float wk = (sub == 0 || sub == 3) ? 1.0f : 2.0f;
            ks0 += wk * k0;
            ks1 += wk * k1;
            if (sub < 3) {
                float cc = (sub == 2) ? dt : 0.5f * dt;
                int dstOff = (sub == 1) ? OFF_HB : OFF_HA;
                if (ksn == 0) {
                    sm[dstOff + jn]        = sm[OFF_H + jn]        + cc * k0;
                    sm[dstOff + HDIM + jn] = sm[OFF_H + HDIM + jn] + cc * k1;
                }
            } else {
                if (ksn == 0) {
                    float s6 = dt * (1.0f / 6.0f);
                    sm[OFF_HODE + jn]        = sm[OFF_H + jn]        + s6 * ks0;
                    sm[OFF_HODE + HDIM + jn] = sm[OFF_H + HDIM + jn] + s6 * ks1;
                }
            }
            __syncthreads();
            srcOff = (sub == 1) ? OFF_HB : OFF_HA;
        }

        // -------- gates: gh = hode @ Whh^T + bhh ; gi = inp @ Wih^T + bih --------
        if (tid < G3) {
            const float* wr = &sm[OFF_WHH + tid * WPITCH];
            float p00 = 0, p01 = 0, p02 = 0, p03 = 0;
            float p10 = 0, p11 = 0, p12 = 0, p13 = 0;
            #pragma unroll
            for (int kk = 0; kk < 32; kk++) {
                const float4 w  = *(const float4*)(wr + kk * 4);
                const float4 h0 = *(const float4*)&sm[OFF_HODE + kk * 4];
                const float4 h1 = *(const float4*)&sm[OFF_HODE + HDIM + kk * 4];
                p00 += w.x * h0.x; p01 += w.y * h0.y; p02 += w.z * h0.z; p03 += w.w * h0.w;
                p10 += w.x * h1.x; p11 += w.y * h1.y; p12 += w.z * h1.z; p13 += w.w * h1.w;
            }
            float gh0 = sm[OFF_BHH + tid] + (p00 + p01) + (p02 + p03);
            float gh1 = sm[OFF_BHH + tid] + (p10 + p11) + (p12 + p13);

            float q00 = 0, q01 = 0, q02 = 0, q03 = 0;
            float q10 = 0, q11 = 0, q12 = 0, q13 = 0;
            #pragma unroll
            for (int c = 0; c < 16; c++) {
                const float4 i0 = *(const float4*)&sm[OFF_INP + c * 4];
                const float4 i1 = *(const float4*)&sm[OFF_INP + DIN + c * 4];
                float2 wa = __half22float2(wih[2 * c]);
                float2 wb = __half22float2(wih[2 * c + 1]);
                q00 += wa.x * i0.x; q01 += wa.y * i0.y; q02 += wb.x * i0.z; q03 += wb.y * i0.w;
                q10 += wa.x * i1.x; q11 += wa.y * i1.y; q12 += wb.x * i1.z; q13 += wb.y * i1.w;
            }
            float gi0 = sm[OFF_BIH + tid] + (q00 + q01) + (q02 + q03);
            float gi1 = sm[OFF_BIH + tid] + (q10 + q11) + (q12 + q13);

            sm[OFF_GGH + tid]      = gh0;
            sm[OFF_GGH + G3 + tid] = gh1;
            sm[OFF_GGI + tid]      = gi0;
            sm[OFF_GGI + G3 + tid] = gi1;
        }
        __syncthreads();

        // -------- GRU combine: h_new --------
        if (tid < 256) {
            int s = tid >> 7, u = tid & 127;
            int go = s * G3;
            float r  = sigm(sm[OFF_GGI + go + u]       + sm[OFF_GGH + go + u]);
            float z  = sigm(sm[OFF_GGI + go + 128 + u] + sm[OFF_GGH + go + 128 + u]);
            float n  = tanh_acc(sm[OFF_GGI + go + 256 + u] + r * sm[OFF_GGH + go + 256 + u]);
            float ho = sm[OFF_HODE + s * HDIM + u];
            sm[OFF_H + s * HDIM + u] = (1.0f - z) * n + z * ho;
        }
        __syncthreads();

        // -------- out row: h_new @ Wout^T + bout (also next step's prev_out) --------
        {
            float b00 = 0, b01 = 0, b02 = 0, b03 = 0;
            float b10 = 0, b11 = 0, b12 = 0, b13 = 0;
            #pragma unroll
            for (int kk = 0; kk < 4; kk++) {
                int rot = (kk + (kso >> 1)) & 3;
                const float4 h0 = *(const float4*)&sm[OFF_H + kso * 16 + rot * 4];
                const float4 h1 = *(const float4*)&sm[OFF_H + HDIM + kso * 16 + rot * 4];
                float w0 = wo[kk * 4 + 0], w1 = wo[kk * 4 + 1];
                float w2 = wo[kk * 4 + 2], w3 = wo[kk * 4 + 3];
                b00 += w0 * h0.x; b01 += w1 * h0.y; b02 += w2 * h0.z; b03 += w3 * h0.w;
                b10 += w0 * h1.x; b11 += w1 * h1.y; b12 += w2 * h1.z; b13 += w3 * h1.w;
            }
            float o0 = (b00 + b01) + (b02 + b03);
            float o1 = (b10 + b11) + (b12 + b13);
            o0 += __shfl_xor_sync(0xffffffffu, o0, 1);
            o0 += __shfl_xor_sync(0xffffffffu, o0, 2);
            o0 += __shfl_xor_sync(0xffffffffu, o0, 4);
            o1 += __shfl_xor_sync(0xffffffffu, o1, 1);
            o1 += __shfl_xor_sync(0xffffffffu, o1, 2);
            o1 += __shfl_xor_sync(0xffffffffu, o1, 4);
            if (kso == 0) {
                float bo = sm[OFF_BOUT + jo];
                sm[OFF_OUT + jo]       = o0 + bo;
                sm[OFF_OUT + DIN + jo] = o1 + bo;
            }
        }
        __syncthreads();

        // -------- store out row, prefetch next x --------
        if (tid < 128) {
            out[(long)(sg0 + sL) * TS * DIN + (long)t * DIN + cL] = sm[OFF_OUT + tid];
            if (t + 1 < TS)
                xv = x[(long)(sg0 + sL) * TS * DIN + (long)(t + 1) * DIN + cL];
        }
        __syncthreads();
    }
}

extern "C" void kernel_launch(void* const* d_in, const int* in_sizes, int n_in,
                              void* d_out, int out_size)
{
    const float*        x     = (const float*)d_in[0];
    const float*        tp    = (const float*)d_in[1];
    const unsigned int* maskw = (const unsigned int*)d_in[2];
    const float*        Wih   = (const float*)d_in[3];
    const float*        Whh   = (const float*)d_in[4];
    const float*        bih   = (const float*)d_in[5];
    const float*        bhh   = (const float*)d_in[6];
    const float*        Wn    = (const float*)d_in[7];
    const float*        bn    = (const float*)d_in[8];
    const float*        Wo    = (const float*)d_in[9];
    const float*        bo    = (const float*)d_in[10];
    float*              outp  = (float*)d_out;

    cudaFuncSetAttribute(gruode_persist,
                         cudaFuncAttributeMaxDynamicSharedMemorySize, SMEM_BYTES);
    gruode_persist<<<NCTA, NT, SMEM_BYTES>>>(x, tp, maskw, Wih, Whh, bih, bhh,
                                             Wn, bn, Wo, bo, outp);
}

// round 10
// speedup vs baseline: 1.0825x; 1.0825x over previous
#include <cuda_runtime.h>
#include <cuda_fp16.h>

#define NT      512     // threads per CTA
#define NCTA    128     // CTAs (2 samples each)
#define TS      512     // time steps
#define HDIM    128
#define DIN     64
#define G3      384

#define WHH_PITCH 68    // uint32 words per W_hh row (136 halfs, 128 used) ; 68 mod 32 == 4 -> conflict-free
#define WIH_PITCH 36    // uint32 words per W_ih row (72 halfs, 64 used)  ; 36 mod 32 == 4 -> conflict-free

// shared memory layout (float/uint32 word offsets)
#define OFF_WHH16  0                  // 384*68 = 26112 words
#define OFF_WIH16  26112              // 384*36 = 13824 -> end 39936
#define OFF_H      39936              // 256
#define OFF_HA     40192              // 256
#define OFF_HB     40448              // 256
#define OFF_HODE   40704              // 256
#define OFF_GGH    40960              // 768
#define OFF_GGI    41728              // 768
#define OFF_INP    42496              // 128
#define OFF_OUT    42624              // 128
#define OFF_DT     42752              // 512
#define OFF_BN     43264              // 128
#define OFF_BIH    43392              // 384
#define OFF_BHH    43776              // 384
#define OFF_BOUT   44160              // 64
#define OFF_MASK   44224              // 128 words (512 B)
#define SMEM_FLOATS 44352
#define SMEM_BYTES  (SMEM_FLOATS * 4)   // 177,408 B

__device__ __forceinline__ float tanh_fast(float v) {
    float y;
    asm("tanh.approx.f32 %0, %1;" : "=f"(y) : "f"(v));
    return y;
}
__device__ __forceinline__ float sigm(float v) {
    return 1.0f / (1.0f + __expf(-v));
}
__device__ __forceinline__ float tanh_acc(float v) {
    return 1.0f - 2.0f / (__expf(2.0f * v) + 1.0f);
}

__global__ void __launch_bounds__(NT, 1)
gruode_persist(const float* __restrict__ x,
               const float* __restrict__ tp,
               const unsigned int* __restrict__ maskw,
               const float* __restrict__ Wih,
               const float* __restrict__ Whh,
               const float* __restrict__ bih,
               const float* __restrict__ bhh,
               const float* __restrict__ Wnode,
               const float* __restrict__ bnode,
               const float* __restrict__ Wout,
               const float* __restrict__ bout,
               float* __restrict__ out)
{
    extern __shared__ float sm[];
    unsigned int* smu = (unsigned int*)sm;
    const int tid = threadIdx.x;
    const int cta = blockIdx.x;
    const int sg0 = cta * 2;

    // ---------------- init: W_hh -> smem fp16 (padded pitch) ----------------
    for (int idx = tid; idx < G3 * 64; idx += NT) {          // 64 half2 words per row
        int r = idx >> 6, kw = idx & 63;
        __half2 hv = __floats2half2_rn(Whh[r * HDIM + 2 * kw], Whh[r * HDIM + 2 * kw + 1]);
        *((__half2*)(smu + OFF_WHH16 + r * WHH_PITCH + kw)) = hv;
    }
    // W_ih -> smem fp16
    for (int idx = tid; idx < G3 * 32; idx += NT) {          // 32 half2 words per row
        int r = idx >> 5, kw = idx & 31;
        __half2 hv = __floats2half2_rn(Wih[r * DIN + 2 * kw], Wih[r * DIN + 2 * kw + 1]);
        *((__half2*)(smu + OFF_WIH16 + r * WIH_PITCH + kw)) = hv;
    }
    for (int i = tid; i < HDIM; i += NT) sm[OFF_BN + i] = bnode[i];
    for (int i = tid; i < G3;   i += NT) { sm[OFF_BIH + i] = bih[i]; sm[OFF_BHH + i] = bhh[i]; }
    for (int i = tid; i < DIN;  i += NT) sm[OFF_BOUT + i] = bout[i];
    if (tid < TS) sm[OFF_DT + tid] = (tid == 0) ? 0.01f : (tp[tid] - tp[tid - 1]);

    // samp_mask layout detection: 0=int32, 1=byte, 2=float32
    __shared__ int layoutFlag;
    if (tid == 0) {
        int fl = 0;
        for (int i = 0; i < 128; i++) {
            unsigned w = maskw[i];
            if (w == 0x3F800000u) { fl = 2; break; }
            if (w > 1u) fl = 1;
        }
        layoutFlag = fl;
    }
    __syncthreads();
    {
        int fl = layoutFlag;
        char* mk = (char*)&sm[OFF_MASK];
        if (tid < TS) {
            bool m;
            if (fl == 1)      m = ((const unsigned char*)maskw)[tid] != 0;
            else if (fl == 2) m = ((const float*)maskw)[tid] != 0.0f;
            else              m = maskw[tid] != 0u;
            mk[tid] = m ? 1 : 0;
        }
    }

    // ---------------- register-resident weights ----------------
    // W_node: thread (jn = tid>>2, ksn = tid&3) owns 32 floats, k-rotated read order
    const int jn = tid >> 2, ksn = tid & 3;
    float wn[32];
    #pragma unroll
    for (int kk = 0; kk < 8; kk++) {
        int rot = (kk + 2 * ksn) & 7;
        #pragma unroll
        for (int c = 0; c < 4; c++)
            wn[kk * 4 + c] = Wnode[jn * HDIM + ksn * 32 + rot * 4 + c];
    }
    // W_out: thread (jo = tid>>3, kso = tid&7) owns 16 floats, rotated
    const int jo = tid >> 3, kso = tid & 7;
    float wo[16];
    #pragma unroll
    for (int kk = 0; kk < 4; kk++) {
        int rot = (kk + (kso >> 1)) & 3;
        #pragma unroll
        for (int c = 0; c < 4; c++)
            wo[kk * 4 + c] = Wout[jo * HDIM + kso * 16 + rot * 4 + c];
    }

    // ---------------- state init ----------------
    if (tid < 256) sm[OFF_H + tid] = 0.0f;
    if (tid < 128) sm[OFF_OUT + tid] = sm[OFF_BOUT + (tid & 63)];

    const int sL = tid >> 6, cL = tid & 63;
    float xv = 0.0f;
    if (tid < 128) xv = x[(long)(sg0 + sL) * TS * DIN + cL];
    __syncthreads();

    // hoisted per-thread constants
    const float bnv  = sm[OFF_BN + jn];
    const float bihv = (tid < G3) ? sm[OFF_BIH + tid] : 0.0f;
    const float bhhv = (tid < G3) ? sm[OFF_BHH + tid] : 0.0f;
    const float bov  = sm[OFF_BOUT + jo];
    const char* mk = (const char*)&sm[OFF_MASK];

    // ============================ time loop ============================
    for (int t = 0; t < TS; t++) {
        const float dt = sm[OFF_DT + t];

        // inp = use_x ? x[t] : prev_out
        if (tid < 128) {
            float pv = sm[OFF_OUT + tid];
            sm[OFF_INP + tid] = mk[t] ? xv : pv;
        }

        // -------- RK4: dh/dt = tanh(h @ Wn^T + bn) --------
        float ks0 = 0.0f, ks1 = 0.0f;
        int srcOff = OFF_H;
        #pragma unroll
        for (int sub = 0; sub < 4; sub++) {
            float a00 = 0, a01 = 0, a02 = 0, a03 = 0;
            float a10 = 0, a11 = 0, a12 = 0, a13 = 0;
            #pragma unroll
            for (int kk = 0; kk < 8; kk++) {
                int rot = (kk + 2 * ksn) & 7;
                const float4 h0 = *(const float4*)&sm[srcOff + ksn * 32 + rot * 4];
                const float4 h1 = *(const float4*)&sm[srcOff + HDIM + ksn * 32 + rot * 4];
                float w0 = wn[kk * 4 + 0], w1 = wn[kk * 4 + 1];
                float w2 = wn[kk * 4 + 2], w3 = wn[kk * 4 + 3];
                a00 += w0 * h0.x; a01 += w1 * h0.y; a02 += w2 * h0.z; a03 += w3 * h0.w;
                a10 += w0 * h1.x; a11 += w1 * h1.y; a12 += w2 * h1.z; a13 += w3 * h1.w;
            }
            float y0 = (a00 + a01) + (a02 + a03);
            float y1 = (a10 + a11) + (a12 + a13);
            y0 += __shfl_xor_sync(0xffffffffu, y0, 1);
            y0 += __shfl_xor_sync(0xffffffffu, y0, 2);
            y1 += __shfl_xor_sync(0xffffffffu, y1, 1);
            y1 += __shfl_xor_sync(0xffffffffu, y1, 2);
            float k0 = tanh_fast(y0 + bnv);
            float k1 = tanh_fast(y1 + bnv);
            float wk = (sub == 0 || sub == 3) ? 1.0f : 2.0f;
            ks0 += wk * k0;
            ks1 += wk * k1;
            if (sub < 3) {
                float cc = (sub == 2) ? dt : 0.5f * dt;
                int dstOff = (sub == 1) ? OFF_HB : OFF_HA;
                if (ksn == 0) {
                    sm[dstOff + jn]        = sm[OFF_H + jn]        + cc * k0;
                    sm[dstOff + HDIM + jn] = sm[OFF_H + HDIM + jn] + cc * k1;
                }
            } else {
                if (ksn == 0) {
                    float s6 = dt * (1.0f / 6.0f);
                    sm[OFF_HODE + jn]        = sm[OFF_H + jn]        + s6 * ks0;
                    sm[OFF_HODE + HDIM + jn] = sm[OFF_H + HDIM + jn] + s6 * ks1;
                }
            }
            __syncthreads();
            srcOff = (sub == 1) ? OFF_HB : OFF_HA;
        }

        // -------- gates: gh = hode @ Whh^T (fp16 smem) ; gi = inp @ Wih^T (fp16 smem) --------
        if (tid < G3) {
            const uint4* wr = (const uint4*)(smu + OFF_WHH16 + (unsigned)tid * WHH_PITCH);
            float p00 = 0, p01 = 0, p02 = 0, p03 = 0;
            float p10 = 0, p11 = 0, p12 = 0, p13 = 0;
            #pragma unroll
            for (int kk = 0; kk < 16; kk++) {
                uint4 wv = wr[kk];
                float2 wa = __half22float2(*(const __half2*)&wv.x);
                float2 wb = __half22float2(*(const __half2*)&wv.y);
                float2 wc = __half22float2(*(const __half2*)&wv.z);
                float2 wd = __half22float2(*(const __half2*)&wv.w);
                const float4 h0a = *(const float4*)&sm[OFF_HODE + kk * 8];
                const float4 h0b = *(const float4*)&sm[OFF_HODE + kk * 8 + 4];
                const float4 h1a = *(const float4*)&sm[OFF_HODE + HDIM + kk * 8];
                const float4 h1b = *(const float4*)&sm[OFF_HODE + HDIM + kk * 8 + 4];
                p00 += wa.x * h0a.x; p01 += wa.y * h0a.y; p02 += wb.x * h0a.z; p03 += wb.y * h0a.w;
                p00 += wc.x * h0b.x; p01 += wc.y * h0b.y; p02 += wd.x * h0b.z; p03 += wd.y * h0b.w;
                p10 += wa.x * h1a.x; p11 += wa.y * h1a.y; p12 += wb.x * h1a.z; p13 += wb.y * h1a.w;
                p10 += wc.x * h1b.x; p11 += wc.y * h1b.y; p12 += wd.x * h1b.z; p13 += wd.y * h1b.w;
            }
            float gh0 = bhhv + (p00 + p01) + (p02 + p03);
            float gh1 = bhhv + (p10 + p11) + (p12 + p13);

            const uint4* wir = (const uint4*)(smu + OFF_WIH16 + (unsigned)tid * WIH_PITCH);
            float q00 = 0, q01 = 0, q02 = 0, q03 = 0;
            float q10 = 0, q11 = 0, q12 = 0, q13 = 0;
            #pragma unroll
            for (int kk = 0; kk < 8; kk++) {
                uint4 wv = wir[kk];
                float2 wa = __half22float2(*(const __half2*)&wv.x);
                float2 wb = __half22float2(*(const __half2*)&wv.y);
                float2 wc = __half22float2(*(const __half2*)&wv.z);
                float2 wd = __half22float2(*(const __half2*)&wv.w);
                const float4 i0a = *(const float4*)&sm[OFF_INP + kk * 8];
                const float4 i0b = *(const float4*)&sm[OFF_INP + kk * 8 + 4];
                const float4 i1a = *(const float4*)&sm[OFF_INP + DIN + kk * 8];
                const float4 i1b = *(const float4*)&sm[OFF_INP + DIN + kk * 8 + 4];
                q00 += wa.x * i0a.x; q01 += wa.y * i0a.y; q02 += wb.x * i0a.z; q03 += wb.y * i0a.w;
                q00 += wc.x * i0b.x; q01 += wc.y * i0b.y; q02 += wd.x * i0b.z; q03 += wd.y * i0b.w;
                q10 += wa.x * i1a.x; q11 += wa.y * i1a.y; q12 += wb.x * i1a.z; q13 += wb.y * i1a.w;
                q10 += wc.x * i1b.x; q11 += wc.y * i1b.y; q12 += wd.x * i1b.z; q13 += wd.y * i1b.w;
            }
            float gi0 = bihv + (q00 + q01) + (q02 + q03);
            float gi1 = bihv + (q10 + q11) + (q12 + q13);

            sm[OFF_GGH + tid]      = gh0;
            sm[OFF_GGH + G3 + tid] = gh1;
            sm[OFF_GGI + tid]      = gi0;
            sm[OFF_GGI + G3 + tid] = gi1;
        }
        __syncthreads();

        // -------- GRU combine --------
        if (tid < 256) {
            int s = tid >> 7, u = tid & 127;
            int go = s * G3;
            float r  = sigm(sm[OFF_GGI + go + u]       + sm[OFF_GGH + go + u]);
            float z  = sigm(sm[OFF_GGI + go + 128 + u] + sm[OFF_GGH + go + 128 + u]);
            float n  = tanh_acc(sm[OFF_GGI + go + 256 + u] + r * sm[OFF_GGH + go + 256 + u]);
            float ho = sm[OFF_HODE + s * HDIM + u];
            sm[OFF_H + s * HDIM + u] = (1.0f - z) * n + z * ho;
        }
        __syncthreads();

        // -------- out row: h_new @ Wout^T + bout --------
        {
            float b00 = 0, b01 = 0, b02 = 0, b03 = 0;
            float b10 = 0, b11 = 0, b12 = 0, b13 = 0;
            #pragma unroll
            for (int kk = 0; kk < 4; kk++) {
                int rot = (kk + (kso >> 1)) & 3;
                const float4 h0 = *(const float4*)&sm[OFF_H + kso * 16 + rot * 4];
                const float4 h1 = *(const float4*)&sm[OFF_H + HDIM + kso * 16 + rot * 4];
                float w0 = wo[kk * 4 + 0], w1 = wo[kk * 4 + 1];
                float w2 = wo[kk * 4 + 2], w3 = wo[kk * 4 + 3];
                b00 += w0 * h0.x; b01 += w1 * h0.y; b02 += w2 * h0.z; b03 += w3 * h0.w;
                b10 += w0 * h1.x; b11 += w1 * h1.y; b12 += w2 * h1.z; b13 += w3 * h1.w;
            }
            float o0 = (b00 + b01) + (b02 + b03);
            float o1 = (b10 + b11) + (b12 + b13);
            o0 += __shfl_xor_sync(0xffffffffu, o0, 1);
            o0 += __shfl_xor_sync(0xffffffffu, o0, 2);
            o0 += __shfl_xor_sync(0xffffffffu, o0, 4);
            o1 += __shfl_xor_sync(0xffffffffu, o1, 1);
            o1 += __shfl_xor_sync(0xffffffffu, o1, 2);
            o1 += __shfl_xor_sync(0xffffffffu, o1, 4);
            if (kso == 0) {
                sm[OFF_OUT + jo]       = o0 + bov;
                sm[OFF_OUT + DIN + jo] = o1 + bov;
            }
        }
        __syncthreads();

        // -------- store out row, prefetch next x --------
        if (tid < 128) {
            out[(long)(sg0 + sL) * TS * DIN + (long)t * DIN + cL] = sm[OFF_OUT + tid];
            if (t + 1 < TS)
                xv = x[(long)(sg0 + sL) * TS * DIN + (long)(t + 1) * DIN + cL];
        }
        __syncthreads();
    }
}

extern "C" void kernel_launch(void* const* d_in, const int* in_sizes, int n_in,
                              void* d_out, int out_size)
{
    const float*        x     = (const float*)d_in[0];
    const float*        tp    = (const float*)d_in[1];
    const unsigned int* maskw = (const unsigned int*)d_in[2];
    const float*        Wih   = (const float*)d_in[3];
    const float*        Whh   = (const float*)d_in[4];
    const float*        bih   = (const float*)d_in[5];
    const float*        bhh   = (const float*)d_in[6];
    const float*        Wn    = (const float*)d_in[7];
    const float*        bn    = (const float*)d_in[8];
    const float*        Wo    = (const float*)d_in[9];
    const float*        bo    = (const float*)d_in[10];
    float*              outp  = (float*)d_out;

    cudaFuncSetAttribute(gruode_persist,
                         cudaFuncAttributeMaxDynamicSharedMemorySize, SMEM_BYTES);
    gruode_persist<<<NCTA, NT, SMEM_BYTES>>>(x, tp, maskw, Wih, Whh, bih, bhh,
                                             Wn, bn, Wo, bo, outp);
}